// round 1
// baseline (speedup 1.0000x reference)
#include <cuda_runtime.h>
#include <stdint.h>

// Problem constants (fixed by the reference)
#define NC    32      // codebooks
#define KC    16      // centroids per codebook
#define DSUB  128     // subvector dim
#define INF   4096    // in features
#define OF    2048    // out features
#define MAXTOK 2048   // BATCH*SEQ

// Scratch: device globals (no allocation allowed)
__device__ float         g_lut[NC * KC * OF];     // 4 MB: lut[c][k][o]
__device__ unsigned char g_idx[MAXTOK * NC];      // idx[token][c]

// ---------------------------------------------------------------------------
// K1: lut[c,k,o] = sum_d cent[c,k,d] * weight[c,d,o]
// grid (OF/256, NC), 128 threads; each thread owns 2 o-columns, 16 k-accums.
// ---------------------------------------------------------------------------
__global__ void lut_kernel(const float* __restrict__ cent,
                           const float* __restrict__ weight)
{
    __shared__ float cst[DSUB * KC];   // transposed: cst[d][k]
    const int c   = blockIdx.y;
    const int tid = threadIdx.x;

    for (int i = tid; i < KC * DSUB; i += 128) {
        int k = i >> 7, d = i & 127;
        cst[d * KC + k] = cent[(c * KC + k) * DSUB + d];
    }
    __syncthreads();

    const int o0 = blockIdx.x * 256 + tid * 2;
    float2 acc[KC];
#pragma unroll
    for (int k = 0; k < KC; k++) acc[k] = make_float2(0.f, 0.f);

    const float* wp = weight + (size_t)c * DSUB * OF + o0;
#pragma unroll 4
    for (int d = 0; d < DSUB; d++) {
        float2 w = *(const float2*)(wp + (size_t)d * OF);
#pragma unroll
        for (int k = 0; k < KC; k++) {
            float cv = cst[d * KC + k];
            acc[k].x = fmaf(cv, w.x, acc[k].x);
            acc[k].y = fmaf(cv, w.y, acc[k].y);
        }
    }
#pragma unroll
    for (int k = 0; k < KC; k++)
        *(float2*)&g_lut[(size_t)(c * KC + k) * OF + o0] = acc[k];
}

// ---------------------------------------------------------------------------
// K2: idx[token][c] = argmin_k ( c2[k] - 2 * <x_sub, cent_k> )
// grid (ntok/128, NC), 128 threads; thread = one token.
// x tile staged in smem (stride 129 -> conflict-free), centroids transposed.
// Near-ties (gap < 1e-2) re-resolved in fp64 so the argmin is exact.
// ---------------------------------------------------------------------------
__global__ void idx_kernel(const float* __restrict__ x,
                           const float* __restrict__ cent)
{
    extern __shared__ float sm[];
    float* xs  = sm;                      // 128 * 129
    float* cst = sm + 128 * 129;          // DSUB * KC (transposed)
    float* c2p = cst + DSUB * KC;         // 16 * 8 partials
    float* c2s = c2p + 16 * 8;            // 16

    const int c   = blockIdx.y;
    const int tb  = blockIdx.x * 128;
    const int tid = threadIdx.x;

    for (int i = tid; i < KC * DSUB; i += 128) {
        int k = i >> 7, d = i & 127;
        cst[d * KC + k] = cent[(c * KC + k) * DSUB + d];
    }
    // stage x tile: 128 tokens x 128 dims, coalesced float4 loads
    for (int i = tid; i < 128 * DSUB / 4; i += 128) {
        int e   = i * 4;
        int row = e >> 7;
        int col = e & 127;
        float4 v = *(const float4*)&x[(size_t)(tb + row) * INF + c * DSUB + col];
        float* dst = &xs[row * 129 + col];
        dst[0] = v.x; dst[1] = v.y; dst[2] = v.z; dst[3] = v.w;
    }
    __syncthreads();

    // c2[k] = sum_d cent^2 : 8-way parallel partials per k
    {
        int k = tid >> 3, part = tid & 7;
        float s = 0.f;
        for (int d = part * 16; d < part * 16 + 16; d++) {
            float cv = cst[d * KC + k];
            s = fmaf(cv, cv, s);
        }
        c2p[k * 8 + part] = s;
    }
    __syncthreads();
    if (tid < 16) {
        float s = 0.f;
        for (int p = 0; p < 8; p++) s += c2p[tid * 8 + p];
        c2s[tid] = s;
    }
    __syncthreads();

    float acc[KC];
#pragma unroll
    for (int k = 0; k < KC; k++) acc[k] = 0.f;

    const float* xr = &xs[tid * 129];
#pragma unroll 2
    for (int d = 0; d < DSUB; d++) {
        float xv = xr[d];
#pragma unroll
        for (int k = 0; k < KC; k++)
            acc[k] = fmaf(xv, cst[d * KC + k], acc[k]);
    }

    // argmin with runner-up tracking (first-min tie-break, like jnp.argmin)
    float best = 1e30f, second = 1e30f;
    int bi = 0, si = 0;
#pragma unroll
    for (int k = 0; k < KC; k++) {
        float v = c2s[k] - 2.f * acc[k];
        if (v < best)        { second = best; si = bi; best = v; bi = k; }
        else if (v < second) { second = v; si = k; }
    }
    if (second - best < 1e-2f) {
        // rare near-tie: exact fp64 re-resolution of the two candidates
        double vb = 0.0, vs = 0.0;
        for (int d = 0; d < DSUB; d++) {
            double xv = (double)xr[d];
            double cb = (double)cst[d * KC + bi];
            double cs = (double)cst[d * KC + si];
            vb += cb * (cb - 2.0 * xv);
            vs += cs * (cs - 2.0 * xv);
        }
        if (vs < vb || (vs == vb && si < bi)) bi = si;
    }
    g_idx[(size_t)(tb + tid) * NC + c] = (unsigned char)bi;
}

// ---------------------------------------------------------------------------
// K3: out[n,o] = bias[o] + sum_c lut[c, idx[n][c], o]
// grid (OF/64, ntok/256), 256 threads.
// Stage lut[:, :, o_tile(64)] = 128 KB in smem; stream 256 tokens per block.
// Thread = (token-group tg = tid>>5, o-pair oi = tid&31): float2 gathers.
// ---------------------------------------------------------------------------
__global__ void gather_kernel(float* __restrict__ out,
                              const float* __restrict__ bias)
{
    extern __shared__ float sm[];
    float*         lut_s = sm;                               // NC*KC*64 floats
    unsigned char* idx_s = (unsigned char*)(sm + NC * KC * 64); // 256*32 B

    const int ob  = blockIdx.x * 64;
    const int tb  = blockIdx.y * 256;
    const int tid = threadIdx.x;

    // stage lut slice: 512 rows x 64 floats, float4 coalesced
    for (int i = tid; i < NC * KC * 64 / 4; i += 256) {
        int row = i >> 4;
        int col = (i & 15) * 4;
        float4 v = *(const float4*)&g_lut[(size_t)row * OF + ob + col];
        *(float4*)&lut_s[row * 64 + col] = v;
    }
    // stage idx tile: 8 KB
    {
        const uint4* src = (const uint4*)&g_idx[(size_t)tb * NC];
        uint4* dst = (uint4*)idx_s;
        for (int i = tid; i < (256 * NC) / 16; i += 256) dst[i] = src[i];
    }
    __syncthreads();

    const int oi = tid & 31;   // o-pair index: columns oi*2, oi*2+1
    const int tg = tid >> 5;   // token group 0..7
    const float2 bv = *(const float2*)&bias[ob + oi * 2];

    for (int t = tg; t < 256; t += 8) {
        uint4 a = *(const uint4*)&idx_s[t * NC];
        uint4 b = *(const uint4*)&idx_s[t * NC + 16];
        unsigned int iw[8] = {a.x, a.y, a.z, a.w, b.x, b.y, b.z, b.w};
        float sx0 = 0.f, sy0 = 0.f, sx1 = 0.f, sy1 = 0.f;
#pragma unroll
        for (int c = 0; c < NC; c++) {
            unsigned int k = (iw[c >> 2] >> ((c & 3) * 8)) & 0xFFu;
            float2 v = *(const float2*)&lut_s[(c * KC + k) * 64 + oi * 2];
            if (c & 1) { sx1 += v.x; sy1 += v.y; }
            else       { sx0 += v.x; sy0 += v.y; }
        }
        float2 r;
        r.x = sx0 + sx1 + bv.x;
        r.y = sy0 + sy1 + bv.y;
        *(float2*)&out[(size_t)(tb + t) * OF + ob + oi * 2] = r;
    }
}

// ---------------------------------------------------------------------------
extern "C" void kernel_launch(void* const* d_in, const int* in_sizes, int n_in,
                              void* d_out, int out_size)
{
    const float* x      = (const float*)d_in[0];
    const float* cent   = (const float*)d_in[1];
    const float* weight = (const float*)d_in[2];
    // d_in[3] = inverse_temperature_logit: dead in the forward value path (STE)
    const float* bias   = (const float*)d_in[4];
    float* out = (float*)d_out;

    const int ntok = in_sizes[0] / INF;   // 2048

    const int IDX_SMEM = (128 * 129 + DSUB * KC + 16 * 8 + 16) * (int)sizeof(float);
    const int G_SMEM   = NC * KC * 64 * (int)sizeof(float) + 256 * NC;

    cudaFuncSetAttribute(idx_kernel,    cudaFuncAttributeMaxDynamicSharedMemorySize, IDX_SMEM);
    cudaFuncSetAttribute(gather_kernel, cudaFuncAttributeMaxDynamicSharedMemorySize, G_SMEM);

    lut_kernel<<<dim3(OF / 256, NC), 128>>>(cent, weight);
    idx_kernel<<<dim3(ntok / 128, NC), 128, IDX_SMEM>>>(x, cent);
    gather_kernel<<<dim3(OF / 64, ntok / 256), 256, G_SMEM>>>(out, bias);
}